// round 15
// baseline (speedup 1.0000x reference)
#include <cuda_runtime.h>
#include <math.h>

#define T_LEN 256
#define BATCH 512
#define ADIM 32
#define ZDIM 16
#define HID 128
#define TB (T_LEN*BATCH)
#define NBLK 128
#define HPITCH 68

static constexpr long long SZ_MEANS = (long long)TB * ZDIM;
static constexpr long long SZ_COVS  = (long long)TB * ZDIM * ZDIM;
static constexpr long long SZ_AS    = (long long)(T_LEN+1) * BATCH * ZDIM * ZDIM;
static constexpr long long SZ_CS    = (long long)(T_LEN+1) * BATCH * ADIM * ZDIM;
static constexpr long long OFF_MEANS = 0;
static constexpr long long OFF_COVS  = OFF_MEANS + SZ_MEANS;
static constexpr long long OFF_NM    = OFF_COVS + SZ_COVS;
static constexpr long long OFF_NC    = OFF_NM + SZ_MEANS;
static constexpr long long OFF_AS    = OFF_NC + SZ_COVS;
static constexpr long long OFF_CS    = OFF_AS + SZ_AS;

// ---------------- device scratch ----------------
__device__ float g_WT0[160 * 512];
__device__ float g_WT1[256 * 512];
__device__ float g_h0T[2 * 128 * 512];
__device__ float g_h1T[2 * 128 * 512];
__device__ float g_h1all[(size_t)TB * 128];
__device__ float g_b0[512], g_b1[512];
__device__ float g_wall[(T_LEN + 1) * BATCH * 3];
__device__ float g_Q[ZDIM * ZDIM];
__device__ float g_R[ADIM * ADIM];
__device__ unsigned g_arrive;
__device__ volatile unsigned g_release;

// ---------------- prep ----------------
__global__ void prep_kernel(const float* __restrict__ QL, const float* __restrict__ RL,
                            const float* __restrict__ Wih0, const float* __restrict__ Whh0,
                            const float* __restrict__ bih0, const float* __restrict__ bhh0,
                            const float* __restrict__ Wih1, const float* __restrict__ Whh1,
                            const float* __restrict__ bih1, const float* __restrict__ bhh1)
{
    int gid = blockIdx.x * blockDim.x + threadIdx.x;
    int gsz = gridDim.x * blockDim.x;
    for (int i = gid; i < 160 * 512; i += gsz) {
        int k = i >> 9, c = i & 511, j = c >> 2, g = c & 3;
        g_WT0[i] = (k < 32) ? Wih0[(g * HID + j) * ADIM + k]
                            : Whh0[(g * HID + j) * HID + (k - 32)];
    }
    for (int i = gid; i < 256 * 512; i += gsz) {
        int k = i >> 9, c = i & 511, j = c >> 2, g = c & 3;
        g_WT1[i] = (k < 128) ? Wih1[(g * HID + j) * HID + k]
                             : Whh1[(g * HID + j) * HID + (k - 128)];
    }
    for (int i = gid; i < 512; i += gsz) {
        int j = i >> 2, g = i & 3, s = g * HID + j;
        g_b0[i] = bih0[s] + bhh0[s];
        g_b1[i] = bih1[s] + bhh1[s];
    }
    for (int i = gid; i < 2 * 128 * 512; i += gsz) { g_h0T[i] = 0.f; g_h1T[i] = 0.f; }
    for (int i = gid; i < BATCH * 3; i += gsz) g_wall[i] = 1.0f;
    for (int i = gid; i < ZDIM * ZDIM; i += gsz) {
        int r = i >> 4, c = i & 15;
        float s = (r == c) ? 1e-3f : 0.f;
        for (int k = 0; k < ZDIM; k++) s += QL[r * ZDIM + k] * QL[c * ZDIM + k];
        g_Q[i] = s;
    }
    for (int i = gid; i < ADIM * ADIM; i += gsz) {
        int r = i >> 5, c = i & 31;
        float s = (r == c) ? 1e-3f : 0.f;
        for (int k = 0; k < ADIM; k++) s += RL[r * ADIM + k] * RL[c * ADIM + k];
        g_R[i] = s;
    }
    if (gid == 0) { g_arrive = 0u; g_release = 0u; }
}

// ---------------- persistent fused 2-layer LSTM (unchanged from R14) ----------------
__global__ void __launch_bounds__(256) lstm_persistent(const float* __restrict__ x)
{
    extern __shared__ float smdyn[];
    float* W0s = smdyn;
    float* W1s = W0s + 5120;
    float* HsT = W1s + 8192;
    float* bs  = HsT + 4352;

    int tid = threadIdx.x;
    int bid = blockIdx.x;
    int col0 = (bid & 15) * 32;
    int row0 = (bid >> 4) * 64;
    int ty = tid >> 3, tx = tid & 7;
    int tyb = ty * 2, txc = tx * 4;
    int j = (col0 >> 2) + tx;

    for (int e = tid; e < 5120; e += 256)
        W0s[e] = g_WT0[(e >> 5) * 512 + col0 + (e & 31)];
    for (int e = tid; e < 8192; e += 256)
        W1s[e] = g_WT1[(e >> 5) * 512 + col0 + (e & 31)];
    if (tid < 32) bs[tid] = g_b0[col0 + tid];
    else if (tid < 64) bs[tid] = g_b1[col0 + tid - 32];

    int kk0 = tid >> 4, b40 = (tid & 15) * 4;
    int q1x = tid + 256;
    int kk1 = q1x >> 4, b41 = (q1x & 15) * 4;

    float c0a = 0.f, c0b = 0.f, c1a = 0.f, c1b = 0.f;
    __syncthreads();

    for (int k = 0; k <= T_LEN; k++) {
        if (k < T_LEN) {
            float a00 = bs[txc], a01 = bs[txc+1], a02 = bs[txc+2], a03 = bs[txc+3];
            float a10 = a00, a11 = a01, a12 = a02, a13 = a03;
            const float* hprev = g_h0T + (size_t)((k + 1) & 1) * 65536;
            float xr[8];
            size_t xbase = (size_t)k * BATCH * ADIM;
#pragma unroll
            for (int q = 0; q < 8; q++) {
                int e = tid + q * 256;
                xr[q] = __ldg(&x[xbase + (size_t)(row0 + (e >> 5)) * ADIM + (e & 31)]);
            }
            float4 p0, p1;
            for (int ch = 0; ch < 5; ch++) {
                float* buf = HsT + (ch & 1) * 2176;
                if (ch == 0) {
#pragma unroll
                    for (int q = 0; q < 8; q++) {
                        int e = tid + q * 256;
                        buf[(e & 31) * HPITCH + (e >> 5)] = xr[q];
                    }
                } else {
                    *(float4*)&buf[kk0 * HPITCH + b40] = p0;
                    *(float4*)&buf[kk1 * HPITCH + b41] = p1;
                }
                if (ch < 4) {
                    int kb = ch * 32;
                    p0 = __ldcg((const float4*)&hprev[(kb + kk0) * 512 + row0 + b40]);
                    p1 = __ldcg((const float4*)&hprev[(kb + kk1) * 512 + row0 + b41]);
                }
                __syncthreads();
                int wb = ch * 1024;
#pragma unroll
                for (int kk = 0; kk < 32; kk++) {
                    float2 av = *(const float2*)&buf[kk * HPITCH + tyb];
                    float4 bv = *(const float4*)&W0s[wb + kk * 32 + txc];
                    a00 += av.x * bv.x; a01 += av.x * bv.y; a02 += av.x * bv.z; a03 += av.x * bv.w;
                    a10 += av.y * bv.x; a11 += av.y * bv.y; a12 += av.y * bv.z; a13 += av.y * bv.w;
                }
            }
            __syncthreads();
            float* hcur = g_h0T + (size_t)(k & 1) * 65536;
            {
                float ig = 1.f / (1.f + expf(-a00));
                float fg = 1.f / (1.f + expf(-a01));
                float gg = tanhf(a02);
                float og = 1.f / (1.f + expf(-a03));
                float c = fg * c0a + ig * gg; c0a = c;
                hcur[j * 512 + row0 + tyb] = og * tanhf(c);
            }
            {
                float ig = 1.f / (1.f + expf(-a10));
                float fg = 1.f / (1.f + expf(-a11));
                float gg = tanhf(a12);
                float og = 1.f / (1.f + expf(-a13));
                float c = fg * c0b + ig * gg; c0b = c;
                hcur[j * 512 + row0 + tyb + 1] = og * tanhf(c);
            }
        }
        if (k >= 1) {
            int t1 = k - 1;
            float a00 = bs[32+txc], a01 = bs[33+txc], a02 = bs[34+txc], a03 = bs[35+txc];
            float a10 = a00, a11 = a01, a12 = a02, a13 = a03;
            const float* h0in = g_h0T + (size_t)(t1 & 1) * 65536;
            const float* h1in = g_h1T + (size_t)(k & 1) * 65536;
            float4 p0 = __ldcg((const float4*)&h0in[kk0 * 512 + row0 + b40]);
            float4 p1 = __ldcg((const float4*)&h0in[kk1 * 512 + row0 + b41]);
            for (int ch = 0; ch < 8; ch++) {
                float* buf = HsT + (ch & 1) * 2176;
                *(float4*)&buf[kk0 * HPITCH + b40] = p0;
                *(float4*)&buf[kk1 * HPITCH + b41] = p1;
                if (ch < 7) {
                    const float* src = (ch + 1 < 4) ? h0in : h1in;
                    int kb = ((ch + 1) & 3) * 32;
                    p0 = __ldcg((const float4*)&src[(kb + kk0) * 512 + row0 + b40]);
                    p1 = __ldcg((const float4*)&src[(kb + kk1) * 512 + row0 + b41]);
                }
                __syncthreads();
                int wb = ch * 1024;
#pragma unroll
                for (int kk = 0; kk < 32; kk++) {
                    float2 av = *(const float2*)&buf[kk * HPITCH + tyb];
                    float4 bv = *(const float4*)&W1s[wb + kk * 32 + txc];
                    a00 += av.x * bv.x; a01 += av.x * bv.y; a02 += av.x * bv.z; a03 += av.x * bv.w;
                    a10 += av.y * bv.x; a11 += av.y * bv.y; a12 += av.y * bv.z; a13 += av.y * bv.w;
                }
            }
            float* h1cur = g_h1T + (size_t)((k & 1) ^ 1) * 65536;
            {
                float ig = 1.f / (1.f + expf(-a00));
                float fg = 1.f / (1.f + expf(-a01));
                float gg = tanhf(a02);
                float og = 1.f / (1.f + expf(-a03));
                float c = fg * c1a + ig * gg; c1a = c;
                float h = og * tanhf(c);
                h1cur[j * 512 + row0 + tyb] = h;
                g_h1all[((size_t)t1 * 512 + row0 + tyb) * 128 + j] = h;
            }
            {
                float ig = 1.f / (1.f + expf(-a10));
                float fg = 1.f / (1.f + expf(-a11));
                float gg = tanhf(a12);
                float og = 1.f / (1.f + expf(-a13));
                float c = fg * c1b + ig * gg; c1b = c;
                float h = og * tanhf(c);
                h1cur[j * 512 + row0 + tyb + 1] = h;
                g_h1all[((size_t)t1 * 512 + row0 + tyb + 1) * 128 + j] = h;
            }
        }
        __syncthreads();
        if (tid == 0) {
            __threadfence();
            unsigned gen = (unsigned)(k + 1);
            unsigned a = atomicAdd(&g_arrive, 1u);
            if (a == NBLK - 1) {
                atomicExch(&g_arrive, 0u);
                __threadfence();
                g_release = gen;
            } else {
                while (g_release < gen) { }
            }
        }
        __syncthreads();
    }
}

// ---------------- logits + softmax ----------------
__global__ void logits_kernel(const float* __restrict__ Wlin, const float* __restrict__ blin)
{
    int row = blockIdx.x * 4 + (threadIdx.x >> 5);
    int lane = threadIdx.x & 31;
    const float* h = g_h1all + (size_t)row * HID;
    float v0 = h[lane], v1 = h[lane + 32], v2 = h[lane + 64], v3 = h[lane + 96];
    float lg[3];
#pragma unroll
    for (int kk = 0; kk < 3; kk++) {
        const float* w = Wlin + kk * HID;
        float d = v0 * w[lane] + v1 * w[lane + 32] + v2 * w[lane + 64] + v3 * w[lane + 96];
#pragma unroll
        for (int off = 16; off > 0; off >>= 1) d += __shfl_xor_sync(0xffffffffu, d, off);
        lg[kk] = d + blin[kk];
    }
    if (lane == 0) {
        float m = fmaxf(lg[0], fmaxf(lg[1], lg[2]));
        float e0 = expf(lg[0] - m), e1 = expf(lg[1] - m), e2 = expf(lg[2] - m);
        float s = 1.f / (e0 + e1 + e2);
        float* w = g_wall + ((size_t)row + BATCH) * 3;
        w[0] = e0 * s; w[1] = e1 * s; w[2] = e2 * s;
    }
}

// ---------------- edge rows: AS row 0, CS row T ----------------
__global__ void edge_kernel(const float* __restrict__ AK, const float* __restrict__ CK,
                            float* __restrict__ out)
{
    int NTOT = 512 * 256 + 512 * 512;
    int stride = gridDim.x * blockDim.x;
    for (int idx = blockIdx.x * blockDim.x + threadIdx.x; idx < NTOT; idx += stride) {
        if (idx < 131072) {
            int b = idx >> 8, e = idx & 255;
            out[OFF_AS + (size_t)b * 256 + e] = AK[e] + AK[256 + e] + AK[512 + e];
        } else {
            int i2 = idx - 131072;
            int b = i2 >> 9, e = i2 & 511;
            const float* w = g_wall + ((size_t)T_LEN * BATCH + b) * 3;
            out[OFF_CS + ((size_t)T_LEN * BATCH + b) * 512 + e] =
                w[0] * CK[e] + w[1] * CK[512 + e] + w[2] * CK[1024 + e];
        }
    }
}

// ---------------- Kalman: 1 BLOCK (128 thr) per batch element ----------------
__global__ void __launch_bounds__(128) kalman_kernel(
    const float* __restrict__ as_, const float* __restrict__ AK,
    const float* __restrict__ CK, const float* __restrict__ im,
    const float* __restrict__ ic, float* __restrict__ out)
{
    __shared__ float sCK[1632], sAK[816], sR[1056], sQ[272], sS[1056];
    __shared__ float sC[544], sCP[544], sX[544];
    __shared__ float sP[272], sPf[272], sA[272], sTm[272];
    __shared__ float sm[16], smf[16], sres[32];

    int tid = threadIdx.x, l = tid & 31, w = tid >> 5;
    int b = blockIdx.x;

    for (int e = tid; e < 1536; e += 128) {
        int kk = e >> 9, rem = e & 511;
        sCK[kk * 544 + (rem >> 4) * 17 + (rem & 15)] = CK[e];
    }
    for (int e = tid; e < 768; e += 128) {
        int kk = e >> 8, rem = e & 255;
        sAK[kk * 272 + (rem >> 4) * 17 + (rem & 15)] = AK[e];
    }
    for (int e = tid; e < 1024; e += 128) sR[(e >> 5) * 33 + (e & 31)] = g_R[e];
    for (int e = tid; e < 256; e += 128) sQ[(e >> 4) * 17 + (e & 15)] = g_Q[e];
    for (int e = tid; e < 256; e += 128) sP[(e >> 4) * 17 + (e & 15)] = ic[e];
    if (tid < 16) sm[tid] = im[tid];
    __syncthreads();

    for (int t = 0; t < T_LEN; t++) {
        size_t row = (size_t)t * BATCH + b;
        const float* wl = g_wall + row * 3;
        float w0 = wl[0], w1 = wl[1], w2 = wl[2];
        // C + CS out
        for (int e = tid; e < 512; e += 128) {
            int idx = (e >> 4) * 17 + (e & 15);
            float v = w0 * sCK[idx] + w1 * sCK[544 + idx] + w2 * sCK[1088 + idx];
            sC[idx] = v;
            out[OFF_CS + row * 512 + e] = v;
        }
        __syncthreads();
        // CP = C @ P ; residual
        for (int e = tid; e < 512; e += 128) {
            int r = e >> 4, jj = e & 15;
            float s = 0.f;
#pragma unroll
            for (int k = 0; k < 16; k++) s += sC[r * 17 + k] * sP[k * 17 + jj];
            sCP[r * 17 + jj] = s;
        }
        if (tid < 32) {
            float s = as_[row * 32 + tid];
#pragma unroll
            for (int k = 0; k < 16; k++) s -= sC[tid * 17 + k] * sm[k];
            sres[tid] = s;
        }
        __syncthreads();
        // S = CP C^T + R
        for (int e = tid; e < 1024; e += 128) {
            int r = e >> 5, c2 = e & 31;
            float s = sR[r * 33 + c2];
#pragma unroll
            for (int k = 0; k < 16; k++) s += sCP[r * 17 + k] * sC[c2 * 17 + k];
            sS[r * 33 + c2] = s;
        }
        __syncthreads();
        // warp0: register GJ on [S | CP | res]; warps1-3: build A + AS out
        if (w == 0) {
            float Ac[32], Bc[32];
#pragma unroll
            for (int r = 0; r < 32; r++) Ac[r] = sS[r * 33 + l];
#pragma unroll
            for (int r = 0; r < 32; r++)
                Bc[r] = (l < 16) ? sCP[r * 17 + l] : ((l == 16) ? sres[r] : 0.f);
#pragma unroll
            for (int kg = 0; kg < 32; kg++) {
                float pv = __shfl_sync(0xffffffffu, Ac[kg], kg);
                float pinv = __fdividef(1.0f, pv);
                float prA = Ac[kg] * pinv;
                float prB = Bc[kg] * pinv;
                Ac[kg] = prA; Bc[kg] = prB;
#pragma unroll
                for (int r = 0; r < 32; r++) {
                    if (r == kg) continue;
                    float cc = __shfl_sync(0xffffffffu, Ac[r], kg);
                    Ac[r] -= cc * prA;
                    Bc[r] -= cc * prB;
                }
            }
            if (l <= 16) {
#pragma unroll
                for (int r = 0; r < 32; r++) sX[r * 17 + l] = Bc[r];
            }
        } else {
            const float* wa = g_wall + ((size_t)(t + 1) * BATCH + b) * 3;
            float a0 = wa[0], a1 = wa[1], a2 = wa[2];
            for (int e = tid - 32; e < 256; e += 96) {
                int idx = (e >> 4) * 17 + (e & 15);
                float v = a0 * sAK[idx] + a1 * sAK[272 + idx] + a2 * sAK[544 + idx];
                sA[idx] = v;
                out[OFF_AS + ((size_t)(t + 1) * BATCH + b) * 256 + e] = v;
            }
        }
        __syncthreads();
        // m_f ; Pf unsym -> sTm
        if (tid < 16) {
            float s = sm[tid];
#pragma unroll
            for (int r = 0; r < 32; r++) s += sCP[r * 17 + tid] * sX[r * 17 + 16];
            smf[tid] = s;
            out[OFF_MEANS + row * 16 + tid] = s;
        }
        for (int e = tid; e < 256; e += 128) {
            int i = e >> 4, jj = e & 15;
            float s = sP[i * 17 + jj];
#pragma unroll
            for (int r = 0; r < 32; r++) s -= sX[r * 17 + i] * sCP[r * 17 + jj];
            sTm[i * 17 + jj] = s;
        }
        __syncthreads();
        // Pf sym + covs out
        for (int e = tid; e < 256; e += 128) {
            int i = e >> 4, jj = e & 15;
            float v = 0.5f * (sTm[i * 17 + jj] + sTm[jj * 17 + i]);
            sPf[i * 17 + jj] = v;
            out[OFF_COVS + row * 256 + e] = v;
        }
        __syncthreads();
        // Tm = A @ Pf ; m_p
        for (int e = tid; e < 256; e += 128) {
            int i = e >> 4, jj = e & 15;
            float s = 0.f;
#pragma unroll
            for (int k = 0; k < 16; k++) s += sA[i * 17 + k] * sPf[k * 17 + jj];
            sTm[i * 17 + jj] = s;
        }
        if (tid < 16) {
            float s = 0.f;
#pragma unroll
            for (int k = 0; k < 16; k++) s += sA[tid * 17 + k] * smf[k];
            sm[tid] = s;
            out[OFF_NM + row * 16 + tid] = s;
        }
        __syncthreads();
        // Pp unsym -> sX
        for (int e = tid; e < 256; e += 128) {
            int i = e >> 4, jj = e & 15;
            float s = sQ[i * 17 + jj];
#pragma unroll
            for (int k = 0; k < 16; k++) s += sTm[i * 17 + k] * sA[jj * 17 + k];
            sX[i * 17 + jj] = s;
        }
        __syncthreads();
        // Pp sym -> P, NC out
        for (int e = tid; e < 256; e += 128) {
            int i = e >> 4, jj = e & 15;
            float v = 0.5f * (sX[i * 17 + jj] + sX[jj * 17 + i]);
            sP[i * 17 + jj] = v;
            out[OFF_NC + row * 256 + e] = v;
        }
        __syncthreads();
    }
}

extern "C" void kernel_launch(void* const* d_in, const int* in_sizes, int n_in,
                              void* d_out, int out_size) {
    const float* as_  = (const float*)d_in[0];
    const float* AK   = (const float*)d_in[1];
    const float* CK   = (const float*)d_in[2];
    const float* QL   = (const float*)d_in[3];
    const float* RL   = (const float*)d_in[4];
    const float* Wih0 = (const float*)d_in[5];
    const float* Whh0 = (const float*)d_in[6];
    const float* bih0 = (const float*)d_in[7];
    const float* bhh0 = (const float*)d_in[8];
    const float* Wih1 = (const float*)d_in[9];
    const float* Whh1 = (const float*)d_in[10];
    const float* bih1 = (const float*)d_in[11];
    const float* bhh1 = (const float*)d_in[12];
    const float* Wlin = (const float*)d_in[13];
    const float* blin = (const float*)d_in[14];
    const float* im   = (const float*)d_in[15];
    const float* ic   = (const float*)d_in[16];
    float* out = (float*)d_out;

    int smemL = (5120 + 8192 + 4352 + 64) * 4;
    cudaFuncSetAttribute(lstm_persistent, cudaFuncAttributeMaxDynamicSharedMemorySize, smemL);

    prep_kernel<<<256, 256>>>(QL, RL, Wih0, Whh0, bih0, bhh0, Wih1, Whh1, bih1, bhh1);
    lstm_persistent<<<NBLK, 256, smemL>>>(as_);
    logits_kernel<<<TB / 4, 128>>>(Wlin, blin);
    edge_kernel<<<1536, 256>>>(AK, CK, out);
    kalman_kernel<<<BATCH, 128>>>(as_, AK, CK, im, ic, out);
}

// round 16
// speedup vs baseline: 1.2481x; 1.2481x over previous
#include <cuda_runtime.h>
#include <math.h>

#define T_LEN 256
#define BATCH 512
#define ADIM 32
#define ZDIM 16
#define HID 128
#define TB (T_LEN*BATCH)
#define NBLK 128
#define DPITCH 132
#define DBUF 4224

static constexpr long long SZ_MEANS = (long long)TB * ZDIM;
static constexpr long long SZ_COVS  = (long long)TB * ZDIM * ZDIM;
static constexpr long long SZ_AS    = (long long)(T_LEN+1) * BATCH * ZDIM * ZDIM;
static constexpr long long SZ_CS    = (long long)(T_LEN+1) * BATCH * ADIM * ZDIM;
static constexpr long long OFF_MEANS = 0;
static constexpr long long OFF_COVS  = OFF_MEANS + SZ_MEANS;
static constexpr long long OFF_NM    = OFF_COVS + SZ_COVS;
static constexpr long long OFF_NC    = OFF_NM + SZ_MEANS;
static constexpr long long OFF_AS    = OFF_NC + SZ_COVS;
static constexpr long long OFF_CS    = OFF_AS + SZ_AS;

// ---------------- packed f32x2 helpers ----------------
__device__ __forceinline__ void fma2(unsigned long long& acc, unsigned long long a, unsigned long long b) {
    asm("fma.rn.f32x2 %0, %1, %2, %0;" : "+l"(acc) : "l"(a), "l"(b));
}
__device__ __forceinline__ unsigned long long pack2(float lo, float hi) {
    unsigned long long r;
    asm("mov.b64 %0, {%1, %2};" : "=l"(r) : "f"(lo), "f"(hi));
    return r;
}
__device__ __forceinline__ void unpack2(float& lo, float& hi, unsigned long long v) {
    asm("mov.b64 {%0, %1}, %2;" : "=f"(lo), "=f"(hi) : "l"(v));
}

// ---------------- device scratch ----------------
__device__ float g_WT0[160 * 512];
__device__ float g_WT1[256 * 512];
__device__ float g_h0T[2 * 128 * 512];
__device__ float g_h1T[2 * 128 * 512];
__device__ float g_h1all[(size_t)TB * 128];
__device__ float g_b0[512], g_b1[512];
__device__ float g_wall[(T_LEN + 1) * BATCH * 3];
__device__ float g_Q[ZDIM * ZDIM];
__device__ float g_R[ADIM * ADIM];
__device__ unsigned g_arrive;
__device__ volatile unsigned g_release;

// ---------------- prep ----------------
__global__ void prep_kernel(const float* __restrict__ QL, const float* __restrict__ RL,
                            const float* __restrict__ Wih0, const float* __restrict__ Whh0,
                            const float* __restrict__ bih0, const float* __restrict__ bhh0,
                            const float* __restrict__ Wih1, const float* __restrict__ Whh1,
                            const float* __restrict__ bih1, const float* __restrict__ bhh1)
{
    int gid = blockIdx.x * blockDim.x + threadIdx.x;
    int gsz = gridDim.x * blockDim.x;
    for (int i = gid; i < 160 * 512; i += gsz) {
        int k = i >> 9, c = i & 511, j = c >> 2, g = c & 3;
        g_WT0[i] = (k < 32) ? Wih0[(g * HID + j) * ADIM + k]
                            : Whh0[(g * HID + j) * HID + (k - 32)];
    }
    for (int i = gid; i < 256 * 512; i += gsz) {
        int k = i >> 9, c = i & 511, j = c >> 2, g = c & 3;
        g_WT1[i] = (k < 128) ? Wih1[(g * HID + j) * HID + k]
                             : Whh1[(g * HID + j) * HID + (k - 128)];
    }
    for (int i = gid; i < 512; i += gsz) {
        int j = i >> 2, g = i & 3, s = g * HID + j;
        g_b0[i] = bih0[s] + bhh0[s];
        g_b1[i] = bih1[s] + bhh1[s];
    }
    for (int i = gid; i < 2 * 128 * 512; i += gsz) { g_h0T[i] = 0.f; g_h1T[i] = 0.f; }
    for (int i = gid; i < BATCH * 3; i += gsz) g_wall[i] = 1.0f;
    for (int i = gid; i < ZDIM * ZDIM; i += gsz) {
        int r = i >> 4, c = i & 15;
        float s = (r == c) ? 1e-3f : 0.f;
        for (int k = 0; k < ZDIM; k++) s += QL[r * ZDIM + k] * QL[c * ZDIM + k];
        g_Q[i] = s;
    }
    for (int i = gid; i < ADIM * ADIM; i += gsz) {
        int r = i >> 5, c = i & 31;
        float s = (r == c) ? 1e-3f : 0.f;
        for (int k = 0; k < ADIM; k++) s += RL[r * ADIM + k] * RL[c * ADIM + k];
        g_R[i] = s;
    }
    if (gid == 0) { g_arrive = 0u; g_release = 0u; }
}

// ---------------- persistent fused 2-layer LSTM (f32x2 packed math) ----------------
__global__ void __launch_bounds__(256) lstm_persistent(const float* __restrict__ x)
{
    extern __shared__ float smdyn[];
    float* W0s = smdyn;               // 5120
    float* W1s = W0s + 5120;          // 8192
    float* HsT = W1s + 8192;          // 2*4224 duplicated double buffer
    float* bs  = HsT + 2 * DBUF;      // 64

    int tid = threadIdx.x;
    int bid = blockIdx.x;
    int col0 = (bid & 15) * 32;
    int row0 = (bid >> 4) * 64;
    int ty = tid >> 3, tx = tid & 7;
    int tyb = ty * 2, txc = tx * 4;
    int j = (col0 >> 2) + tx;

    for (int e = tid; e < 5120; e += 256)
        W0s[e] = g_WT0[(e >> 5) * 512 + col0 + (e & 31)];
    for (int e = tid; e < 8192; e += 256)
        W1s[e] = g_WT1[(e >> 5) * 512 + col0 + (e & 31)];
    if (tid < 32) bs[tid] = g_b0[col0 + tid];
    else if (tid < 64) bs[tid] = g_b1[col0 + tid - 32];

    int kk0 = tid >> 4, b40 = (tid & 15) * 4;
    int q1x = tid + 256;
    int kk1 = q1x >> 4, b41 = (q1x & 15) * 4;

    float c0a = 0.f, c0b = 0.f, c1a = 0.f, c1b = 0.f;
    __syncthreads();

    for (int k = 0; k <= T_LEN; k++) {
        if (k < T_LEN) {
            unsigned long long accA = pack2(bs[txc], bs[txc+1]);
            unsigned long long accB = pack2(bs[txc+2], bs[txc+3]);
            unsigned long long accC = accA, accD = accB;
            const float* hprev = g_h0T + (size_t)((k + 1) & 1) * 65536;
            float xr[8];
            size_t xbase = (size_t)k * BATCH * ADIM;
#pragma unroll
            for (int q = 0; q < 8; q++) {
                int e = tid + q * 256;
                xr[q] = __ldg(&x[xbase + (size_t)(row0 + (e >> 5)) * ADIM + (e & 31)]);
            }
            float4 p0, p1;
            for (int ch = 0; ch < 5; ch++) {
                float* buf = HsT + (ch & 1) * DBUF;
                if (ch == 0) {
#pragma unroll
                    for (int q = 0; q < 8; q++) {
                        int e = tid + q * 256;
                        int off = (e & 31) * DPITCH + 2 * (e >> 5);
                        buf[off] = xr[q]; buf[off + 1] = xr[q];
                    }
                } else {
                    *(float4*)&buf[kk0 * DPITCH + 2 * b40] = make_float4(p0.x, p0.x, p0.y, p0.y);
                    *(float4*)&buf[kk0 * DPITCH + 2 * b40 + 4] = make_float4(p0.z, p0.z, p0.w, p0.w);
                    *(float4*)&buf[kk1 * DPITCH + 2 * b41] = make_float4(p1.x, p1.x, p1.y, p1.y);
                    *(float4*)&buf[kk1 * DPITCH + 2 * b41 + 4] = make_float4(p1.z, p1.z, p1.w, p1.w);
                }
                if (ch < 4) {
                    int kb = ch * 32;
                    p0 = __ldcg((const float4*)&hprev[(kb + kk0) * 512 + row0 + b40]);
                    p1 = __ldcg((const float4*)&hprev[(kb + kk1) * 512 + row0 + b41]);
                }
                __syncthreads();
                int wb = ch * 1024;
#pragma unroll
                for (int kk = 0; kk < 32; kk++) {
                    ulonglong2 av = *(const ulonglong2*)&buf[kk * DPITCH + 4 * ty];
                    ulonglong2 bv = *(const ulonglong2*)&W0s[wb + kk * 32 + txc];
                    fma2(accA, av.x, bv.x); fma2(accB, av.x, bv.y);
                    fma2(accC, av.y, bv.x); fma2(accD, av.y, bv.y);
                }
            }
            __syncthreads();
            float a00, a01, a02, a03, a10, a11, a12, a13;
            unpack2(a00, a01, accA); unpack2(a02, a03, accB);
            unpack2(a10, a11, accC); unpack2(a12, a13, accD);
            float* hcur = g_h0T + (size_t)(k & 1) * 65536;
            {
                float ig = 1.f / (1.f + expf(-a00));
                float fg = 1.f / (1.f + expf(-a01));
                float gg = tanhf(a02);
                float og = 1.f / (1.f + expf(-a03));
                float c = fg * c0a + ig * gg; c0a = c;
                hcur[j * 512 + row0 + tyb] = og * tanhf(c);
            }
            {
                float ig = 1.f / (1.f + expf(-a10));
                float fg = 1.f / (1.f + expf(-a11));
                float gg = tanhf(a12);
                float og = 1.f / (1.f + expf(-a13));
                float c = fg * c0b + ig * gg; c0b = c;
                hcur[j * 512 + row0 + tyb + 1] = og * tanhf(c);
            }
        }
        if (k >= 1) {
            int t1 = k - 1;
            unsigned long long accA = pack2(bs[32+txc], bs[33+txc]);
            unsigned long long accB = pack2(bs[34+txc], bs[35+txc]);
            unsigned long long accC = accA, accD = accB;
            const float* h0in = g_h0T + (size_t)(t1 & 1) * 65536;
            const float* h1in = g_h1T + (size_t)(k & 1) * 65536;
            float4 p0 = __ldcg((const float4*)&h0in[kk0 * 512 + row0 + b40]);
            float4 p1 = __ldcg((const float4*)&h0in[kk1 * 512 + row0 + b41]);
            for (int ch = 0; ch < 8; ch++) {
                float* buf = HsT + (ch & 1) * DBUF;
                *(float4*)&buf[kk0 * DPITCH + 2 * b40] = make_float4(p0.x, p0.x, p0.y, p0.y);
                *(float4*)&buf[kk0 * DPITCH + 2 * b40 + 4] = make_float4(p0.z, p0.z, p0.w, p0.w);
                *(float4*)&buf[kk1 * DPITCH + 2 * b41] = make_float4(p1.x, p1.x, p1.y, p1.y);
                *(float4*)&buf[kk1 * DPITCH + 2 * b41 + 4] = make_float4(p1.z, p1.z, p1.w, p1.w);
                if (ch < 7) {
                    const float* src = (ch + 1 < 4) ? h0in : h1in;
                    int kb = ((ch + 1) & 3) * 32;
                    p0 = __ldcg((const float4*)&src[(kb + kk0) * 512 + row0 + b40]);
                    p1 = __ldcg((const float4*)&src[(kb + kk1) * 512 + row0 + b41]);
                }
                __syncthreads();
                int wb = ch * 1024;
#pragma unroll
                for (int kk = 0; kk < 32; kk++) {
                    ulonglong2 av = *(const ulonglong2*)&buf[kk * DPITCH + 4 * ty];
                    ulonglong2 bv = *(const ulonglong2*)&W1s[wb + kk * 32 + txc];
                    fma2(accA, av.x, bv.x); fma2(accB, av.x, bv.y);
                    fma2(accC, av.y, bv.x); fma2(accD, av.y, bv.y);
                }
                __syncthreads();
            }
            float a00, a01, a02, a03, a10, a11, a12, a13;
            unpack2(a00, a01, accA); unpack2(a02, a03, accB);
            unpack2(a10, a11, accC); unpack2(a12, a13, accD);
            float* h1cur = g_h1T + (size_t)((k & 1) ^ 1) * 65536;
            {
                float ig = 1.f / (1.f + expf(-a00));
                float fg = 1.f / (1.f + expf(-a01));
                float gg = tanhf(a02);
                float og = 1.f / (1.f + expf(-a03));
                float c = fg * c1a + ig * gg; c1a = c;
                float h = og * tanhf(c);
                h1cur[j * 512 + row0 + tyb] = h;
                g_h1all[((size_t)t1 * 512 + row0 + tyb) * 128 + j] = h;
            }
            {
                float ig = 1.f / (1.f + expf(-a10));
                float fg = 1.f / (1.f + expf(-a11));
                float gg = tanhf(a12);
                float og = 1.f / (1.f + expf(-a13));
                float c = fg * c1b + ig * gg; c1b = c;
                float h = og * tanhf(c);
                h1cur[j * 512 + row0 + tyb + 1] = h;
                g_h1all[((size_t)t1 * 512 + row0 + tyb + 1) * 128 + j] = h;
            }
        }
        __syncthreads();
        if (tid == 0) {
            __threadfence();
            unsigned gen = (unsigned)(k + 1);
            unsigned a = atomicAdd(&g_arrive, 1u);
            if (a == NBLK - 1) {
                atomicExch(&g_arrive, 0u);
                __threadfence();
                g_release = gen;
            } else {
                while (g_release < gen) { }
            }
        }
        __syncthreads();
    }
}

// ---------------- logits + softmax ----------------
__global__ void logits_kernel(const float* __restrict__ Wlin, const float* __restrict__ blin)
{
    int row = blockIdx.x * 4 + (threadIdx.x >> 5);
    int lane = threadIdx.x & 31;
    const float* h = g_h1all + (size_t)row * HID;
    float v0 = h[lane], v1 = h[lane + 32], v2 = h[lane + 64], v3 = h[lane + 96];
    float lg[3];
#pragma unroll
    for (int kk = 0; kk < 3; kk++) {
        const float* w = Wlin + kk * HID;
        float d = v0 * w[lane] + v1 * w[lane + 32] + v2 * w[lane + 64] + v3 * w[lane + 96];
#pragma unroll
        for (int off = 16; off > 0; off >>= 1) d += __shfl_xor_sync(0xffffffffu, d, off);
        lg[kk] = d + blin[kk];
    }
    if (lane == 0) {
        float m = fmaxf(lg[0], fmaxf(lg[1], lg[2]));
        float e0 = expf(lg[0] - m), e1 = expf(lg[1] - m), e2 = expf(lg[2] - m);
        float s = 1.f / (e0 + e1 + e2);
        float* w = g_wall + ((size_t)row + BATCH) * 3;
        w[0] = e0 * s; w[1] = e1 * s; w[2] = e2 * s;
    }
}

// ---------------- edge rows: AS row 0, CS row T ----------------
__global__ void edge_kernel(const float* __restrict__ AK, const float* __restrict__ CK,
                            float* __restrict__ out)
{
    int NTOT = 512 * 256 + 512 * 512;
    int stride = gridDim.x * blockDim.x;
    for (int idx = blockIdx.x * blockDim.x + threadIdx.x; idx < NTOT; idx += stride) {
        if (idx < 131072) {
            int b = idx >> 8, e = idx & 255;
            out[OFF_AS + (size_t)b * 256 + e] = AK[e] + AK[256 + e] + AK[512 + e];
        } else {
            int i2 = idx - 131072;
            int b = i2 >> 9, e = i2 & 511;
            const float* w = g_wall + ((size_t)T_LEN * BATCH + b) * 3;
            out[OFF_CS + ((size_t)T_LEN * BATCH + b) * 512 + e] =
                w[0] * CK[e] + w[1] * CK[512 + e] + w[2] * CK[1024 + e];
        }
    }
}

// ---------------- Kalman: 1 WARP per batch element (R14 version + load hoist) ----------------
__global__ void __launch_bounds__(128) kalman_kernel(
    const float* __restrict__ as_, const float* __restrict__ AK,
    const float* __restrict__ CK, const float* __restrict__ im,
    const float* __restrict__ ic, float* __restrict__ out)
{
    extern __shared__ float sm[];
    float* sCK = sm;
    float* sAK = sCK + 1632;
    float* sR  = sAK + 816;
    float* sQ  = sR + 1056;
    float* wsAll = sQ + 272;

    int tid = threadIdx.x, wid = tid >> 5, l = tid & 31;
    int b = blockIdx.x * 4 + wid;
    float* P  = wsAll + wid * 2176;
    float* CP = P + 272;
    float* X  = CP + 544;
    float* Pf = X + 544;
    float* A  = Pf + 272;
    float* Tm = A + 272;

    for (int e = tid; e < 1536; e += 128) {
        int kk = e >> 9, rem = e & 511;
        sCK[kk * 544 + (rem >> 4) * 17 + (rem & 15)] = CK[e];
    }
    for (int e = tid; e < 768; e += 128) {
        int kk = e >> 8, rem = e & 255;
        sAK[kk * 272 + (rem >> 4) * 17 + (rem & 15)] = AK[e];
    }
    for (int e = tid; e < 1024; e += 128) sR[(e >> 5) * 33 + (e & 31)] = g_R[e];
    for (int e = tid; e < 256; e += 128) sQ[(e >> 4) * 17 + (e & 15)] = g_Q[e];
    for (int e = l; e < 256; e += 32) P[(e >> 4) * 17 + (e & 15)] = ic[e];
    float m[16];
#pragma unroll
    for (int k = 0; k < 16; k++) m[k] = im[k];
    __syncthreads();

    int i_ = l >> 1, j0 = (l & 1) * 8;

    for (int t = 0; t < T_LEN; t++) {
        size_t row = (size_t)t * BATCH + b;
        const float* wl = g_wall + row * 3;
        float w0 = wl[0], w1 = wl[1], w2 = wl[2];
        const float* wa = g_wall + ((size_t)(t + 1) * BATCH + b) * 3;
        float a0 = __ldg(&wa[0]), a1 = __ldg(&wa[1]), a2 = __ldg(&wa[2]);
        float aobs = __ldg(&as_[row * 32 + l]);
        // C row l, write CS output
        float c[16];
#pragma unroll
        for (int k = 0; k < 16; k++)
            c[k] = w0 * sCK[l*17+k] + w1 * sCK[544 + l*17+k] + w2 * sCK[1088 + l*17+k];
        {
            float4* dst = (float4*)(out + OFF_CS + row * 512 + l * 16);
            dst[0] = make_float4(c[0], c[1], c[2], c[3]);
            dst[1] = make_float4(c[4], c[5], c[6], c[7]);
            dst[2] = make_float4(c[8], c[9], c[10], c[11]);
            dst[3] = make_float4(c[12], c[13], c[14], c[15]);
        }
        // CPo row l
        float cp[16];
#pragma unroll
        for (int jj = 0; jj < 16; jj++) cp[jj] = 0.f;
#pragma unroll
        for (int k = 0; k < 16; k++) {
            float ck = c[k];
#pragma unroll
            for (int jj = 0; jj < 16; jj++) cp[jj] += ck * P[k*17+jj];
        }
#pragma unroll
        for (int jj = 0; jj < 16; jj++) CP[l*17+jj] = cp[jj];
        // residual
        float res = aobs;
#pragma unroll
        for (int k = 0; k < 16; k++) res -= c[k] * m[k];
        __syncwarp();
        // S column l, B columns
        float Ac[32], Bc[32];
#pragma unroll
        for (int r = 0; r < 32; r++) {
            float s = sR[r*33 + l];
#pragma unroll
            for (int k = 0; k < 16; k++) s += CP[r*17+k] * c[k];
            Ac[r] = s;
        }
#pragma unroll
        for (int r = 0; r < 32; r++) Bc[r] = (l < 16) ? CP[r*17+l] : 0.f;
#pragma unroll
        for (int r = 0; r < 32; r++) {
            float rr = __shfl_sync(0xffffffffu, res, r);
            if (l == 16) Bc[r] = rr;
        }
        // Gauss-Jordan (S SPD, no pivoting), column-per-lane
#pragma unroll
        for (int kg = 0; kg < 32; kg++) {
            float pv = __shfl_sync(0xffffffffu, Ac[kg], kg);
            float pinv = __fdividef(1.0f, pv);
            float prA = Ac[kg] * pinv;
            float prB = Bc[kg] * pinv;
            Ac[kg] = prA; Bc[kg] = prB;
#pragma unroll
            for (int r = 0; r < 32; r++) {
                if (r == kg) continue;
                float cc = __shfl_sync(0xffffffffu, Ac[r], kg);
                Ac[r] -= cc * prA;
                Bc[r] -= cc * prB;
            }
        }
        if (l <= 16) {
#pragma unroll
            for (int r = 0; r < 32; r++) X[r*17 + l] = Bc[r];
        }
        __syncwarp();
        // m_f
        float mf = 0.f;
        if (l < 16) {
            mf = m[l];
#pragma unroll
            for (int r = 0; r < 32; r++) mf += CP[r*17+l] * X[r*17+16];
            out[OFF_MEANS + row * 16 + l] = mf;
        }
#pragma unroll
        for (int k = 0; k < 16; k++) m[k] = __shfl_sync(0xffffffffu, mf, k);
        // Pf unsym -> Tm
        {
            float v[8];
#pragma unroll
            for (int jj = 0; jj < 8; jj++) {
                int jc = j0 + jj;
                float s = P[i_*17+jc];
#pragma unroll
                for (int r = 0; r < 32; r++) s -= X[r*17+i_] * CP[r*17+jc];
                v[jj] = s;
            }
#pragma unroll
            for (int jj = 0; jj < 8; jj++) Tm[i_*17+j0+jj] = v[jj];
        }
        __syncwarp();
        // sym Pf + covs out ; A formation + AS(t+1) out
        {
            float v[8], u[8];
#pragma unroll
            for (int jj = 0; jj < 8; jj++) {
                int jc = j0 + jj;
                v[jj] = 0.5f * (Tm[i_*17+jc] + Tm[jc*17+i_]);
                Pf[i_*17+jc] = v[jj];
                u[jj] = a0 * sAK[i_*17+jc] + a1 * sAK[272 + i_*17+jc] + a2 * sAK[544 + i_*17+jc];
                A[i_*17+jc] = u[jj];
            }
            float4* d1 = (float4*)(out + OFF_COVS + row * 256 + l * 8);
            d1[0] = make_float4(v[0], v[1], v[2], v[3]);
            d1[1] = make_float4(v[4], v[5], v[6], v[7]);
            float4* d2 = (float4*)(out + OFF_AS + ((size_t)(t + 1) * BATCH + b) * 256 + l * 8);
            d2[0] = make_float4(u[0], u[1], u[2], u[3]);
            d2[1] = make_float4(u[4], u[5], u[6], u[7]);
        }
        __syncwarp();
        // m_p
        float mp = 0.f;
        if (l < 16) {
#pragma unroll
            for (int k = 0; k < 16; k++) mp += A[l*17+k] * m[k];
            out[OFF_NM + row * 16 + l] = mp;
        }
        // Tm = A @ Pf
        {
            float v[8];
#pragma unroll
            for (int jj = 0; jj < 8; jj++) {
                int jc = j0 + jj;
                float s = 0.f;
#pragma unroll
                for (int k = 0; k < 16; k++) s += A[i_*17+k] * Pf[k*17+jc];
                v[jj] = s;
            }
#pragma unroll
            for (int jj = 0; jj < 8; jj++) Tm[i_*17+j0+jj] = v[jj];
        }
#pragma unroll
        for (int k = 0; k < 16; k++) m[k] = __shfl_sync(0xffffffffu, mp, k);
        __syncwarp();
        // Pp unsym -> X
        {
            float v[8];
#pragma unroll
            for (int jj = 0; jj < 8; jj++) {
                int jc = j0 + jj;
                float s = sQ[i_*17+jc];
#pragma unroll
                for (int k = 0; k < 16; k++) s += Tm[i_*17+k] * A[jc*17+k];
                v[jj] = s;
            }
#pragma unroll
            for (int jj = 0; jj < 8; jj++) X[i_*17+j0+jj] = v[jj];
        }
        __syncwarp();
        // sym Pp -> P, NC out
        {
            float v[8];
#pragma unroll
            for (int jj = 0; jj < 8; jj++) {
                int jc = j0 + jj;
                v[jj] = 0.5f * (X[i_*17+jc] + X[jc*17+i_]);
                P[i_*17+jc] = v[jj];
            }
            float4* d = (float4*)(out + OFF_NC + row * 256 + l * 8);
            d[0] = make_float4(v[0], v[1], v[2], v[3]);
            d[1] = make_float4(v[4], v[5], v[6], v[7]);
        }
        __syncwarp();
    }
}

extern "C" void kernel_launch(void* const* d_in, const int* in_sizes, int n_in,
                              void* d_out, int out_size) {
    const float* as_  = (const float*)d_in[0];
    const float* AK   = (const float*)d_in[1];
    const float* CK   = (const float*)d_in[2];
    const float* QL   = (const float*)d_in[3];
    const float* RL   = (const float*)d_in[4];
    const float* Wih0 = (const float*)d_in[5];
    const float* Whh0 = (const float*)d_in[6];
    const float* bih0 = (const float*)d_in[7];
    const float* bhh0 = (const float*)d_in[8];
    const float* Wih1 = (const float*)d_in[9];
    const float* Whh1 = (const float*)d_in[10];
    const float* bih1 = (const float*)d_in[11];
    const float* bhh1 = (const float*)d_in[12];
    const float* Wlin = (const float*)d_in[13];
    const float* blin = (const float*)d_in[14];
    const float* im   = (const float*)d_in[15];
    const float* ic   = (const float*)d_in[16];
    float* out = (float*)d_out;

    int smemL = (5120 + 8192 + 2 * DBUF + 64) * 4;
    int smemK = (1632 + 816 + 1056 + 272 + 4 * 2176) * 4;
    cudaFuncSetAttribute(lstm_persistent, cudaFuncAttributeMaxDynamicSharedMemorySize, smemL);
    cudaFuncSetAttribute(kalman_kernel, cudaFuncAttributeMaxDynamicSharedMemorySize, smemK);

    prep_kernel<<<256, 256>>>(QL, RL, Wih0, Whh0, bih0, bhh0, Wih1, Whh1, bih1, bhh1);
    lstm_persistent<<<NBLK, 256, smemL>>>(as_);
    logits_kernel<<<TB / 4, 128>>>(Wlin, blin);
    edge_kernel<<<1536, 256>>>(AK, CK, out);
    kalman_kernel<<<BATCH / 4, 128, smemK>>>(as_, AK, CK, im, ic, out);
}

// round 17
// speedup vs baseline: 1.8890x; 1.5135x over previous
#include <cuda_runtime.h>
#include <math.h>

#define T_LEN 256
#define BATCH 512
#define ADIM 32
#define ZDIM 16
#define HID 128
#define TB (T_LEN*BATCH)
#define NBLK 128
#define HPITCH 68

static constexpr long long SZ_MEANS = (long long)TB * ZDIM;
static constexpr long long SZ_COVS  = (long long)TB * ZDIM * ZDIM;
static constexpr long long SZ_AS    = (long long)(T_LEN+1) * BATCH * ZDIM * ZDIM;
static constexpr long long SZ_CS    = (long long)(T_LEN+1) * BATCH * ADIM * ZDIM;
static constexpr long long OFF_MEANS = 0;
static constexpr long long OFF_COVS  = OFF_MEANS + SZ_MEANS;
static constexpr long long OFF_NM    = OFF_COVS + SZ_COVS;
static constexpr long long OFF_NC    = OFF_NM + SZ_MEANS;
static constexpr long long OFF_AS    = OFF_NC + SZ_COVS;
static constexpr long long OFF_CS    = OFF_AS + SZ_AS;

// ---------------- device scratch ----------------
__device__ float g_WT0[160 * 512];
__device__ float g_WT1[256 * 512];
__device__ float g_h0T[2 * 128 * 512];
__device__ float g_h1T[2 * 128 * 512];
__device__ float g_h1all[(size_t)TB * 128];
__device__ float g_b0[512], g_b1[512];
__device__ float g_wall[(T_LEN + 1) * BATCH * 3];
__device__ float g_Q[ZDIM * ZDIM];
__device__ float g_R[ADIM * ADIM];
__device__ float g_Rinv[ADIM * ADIM];
__device__ float g_CKR[3 * ZDIM * ADIM];   // CK_k^T @ R^-1  (16x32 each)
__device__ float g_M[9 * ZDIM * ZDIM];     // CKR_j @ CK_k   (16x16 each)
__device__ unsigned g_arrive;
__device__ volatile unsigned g_release;

// ---------------- prep ----------------
__global__ void prep_kernel(const float* __restrict__ QL, const float* __restrict__ RL,
                            const float* __restrict__ Wih0, const float* __restrict__ Whh0,
                            const float* __restrict__ bih0, const float* __restrict__ bhh0,
                            const float* __restrict__ Wih1, const float* __restrict__ Whh1,
                            const float* __restrict__ bih1, const float* __restrict__ bhh1)
{
    int gid = blockIdx.x * blockDim.x + threadIdx.x;
    int gsz = gridDim.x * blockDim.x;
    for (int i = gid; i < 160 * 512; i += gsz) {
        int k = i >> 9, c = i & 511, j = c >> 2, g = c & 3;
        g_WT0[i] = (k < 32) ? Wih0[(g * HID + j) * ADIM + k]
                            : Whh0[(g * HID + j) * HID + (k - 32)];
    }
    for (int i = gid; i < 256 * 512; i += gsz) {
        int k = i >> 9, c = i & 511, j = c >> 2, g = c & 3;
        g_WT1[i] = (k < 128) ? Wih1[(g * HID + j) * HID + k]
                             : Whh1[(g * HID + j) * HID + (k - 128)];
    }
    for (int i = gid; i < 512; i += gsz) {
        int j = i >> 2, g = i & 3, s = g * HID + j;
        g_b0[i] = bih0[s] + bhh0[s];
        g_b1[i] = bih1[s] + bhh1[s];
    }
    for (int i = gid; i < 2 * 128 * 512; i += gsz) { g_h0T[i] = 0.f; g_h1T[i] = 0.f; }
    for (int i = gid; i < BATCH * 3; i += gsz) g_wall[i] = 1.0f;
    for (int i = gid; i < ZDIM * ZDIM; i += gsz) {
        int r = i >> 4, c = i & 15;
        float s = (r == c) ? 1e-3f : 0.f;
        for (int k = 0; k < ZDIM; k++) s += QL[r * ZDIM + k] * QL[c * ZDIM + k];
        g_Q[i] = s;
    }
    for (int i = gid; i < ADIM * ADIM; i += gsz) {
        int r = i >> 5, c = i & 31;
        float s = (r == c) ? 1e-3f : 0.f;
        for (int k = 0; k < ADIM; k++) s += RL[r * ADIM + k] * RL[c * ADIM + k];
        g_R[i] = s;
    }
    if (gid == 0) { g_arrive = 0u; g_release = 0u; }
}

// ---------------- prep2: Rinv, CKR, M ----------------
__global__ void prep2_kernel(const float* __restrict__ CK)
{
    int tid = threadIdx.x;
    if (tid < 32) {
        int l = tid;
        float Ac[32], Bc[32];
#pragma unroll
        for (int r = 0; r < 32; r++) { Ac[r] = g_R[r * 32 + l]; Bc[r] = (r == l) ? 1.f : 0.f; }
#pragma unroll
        for (int kg = 0; kg < 32; kg++) {
            float pv = __shfl_sync(0xffffffffu, Ac[kg], kg);
            float pinv = 1.0f / pv;
            float prA = Ac[kg] * pinv;
            float prB = Bc[kg] * pinv;
            Ac[kg] = prA; Bc[kg] = prB;
#pragma unroll
            for (int r = 0; r < 32; r++) {
                if (r == kg) continue;
                float cc = __shfl_sync(0xffffffffu, Ac[r], kg);
                Ac[r] -= cc * prA;
                Bc[r] -= cc * prB;
            }
        }
#pragma unroll
        for (int r = 0; r < 32; r++) g_Rinv[r * 32 + l] = Bc[r];
    }
    __syncthreads();
    // CKR[k][z][a] = sum_s CK[k][s][z] * Rinv[s][a]
    for (int i = tid; i < 3 * 16 * 32; i += blockDim.x) {
        int k = i >> 9, rem = i & 511, z = rem >> 5, a = rem & 31;
        float s = 0.f;
        for (int s2 = 0; s2 < 32; s2++)
            s += CK[k * 512 + s2 * 16 + z] * g_Rinv[s2 * 32 + a];
        g_CKR[i] = s;
    }
    __syncthreads();
    // M[j*3+k][z1][z2] = sum_a CKR[j][z1][a] * CK[k][a][z2]
    for (int i = tid; i < 9 * 256; i += blockDim.x) {
        int jk = i >> 8, rem = i & 255, j = jk / 3, k = jk % 3, z1 = rem >> 4, z2 = rem & 15;
        float s = 0.f;
        for (int a = 0; a < 32; a++)
            s += g_CKR[j * 512 + z1 * 32 + a] * CK[k * 512 + a * 16 + z2];
        g_M[i] = s;
    }
}

// ---------------- persistent fused 2-layer LSTM (R14 best version) ----------------
__global__ void __launch_bounds__(256) lstm_persistent(const float* __restrict__ x)
{
    extern __shared__ float smdyn[];
    float* W0s = smdyn;
    float* W1s = W0s + 5120;
    float* HsT = W1s + 8192;
    float* bs  = HsT + 4352;

    int tid = threadIdx.x;
    int bid = blockIdx.x;
    int col0 = (bid & 15) * 32;
    int row0 = (bid >> 4) * 64;
    int ty = tid >> 3, tx = tid & 7;
    int tyb = ty * 2, txc = tx * 4;
    int j = (col0 >> 2) + tx;

    for (int e = tid; e < 5120; e += 256)
        W0s[e] = g_WT0[(e >> 5) * 512 + col0 + (e & 31)];
    for (int e = tid; e < 8192; e += 256)
        W1s[e] = g_WT1[(e >> 5) * 512 + col0 + (e & 31)];
    if (tid < 32) bs[tid] = g_b0[col0 + tid];
    else if (tid < 64) bs[tid] = g_b1[col0 + tid - 32];

    int kk0 = tid >> 4, b40 = (tid & 15) * 4;
    int q1x = tid + 256;
    int kk1 = q1x >> 4, b41 = (q1x & 15) * 4;

    float c0a = 0.f, c0b = 0.f, c1a = 0.f, c1b = 0.f;
    __syncthreads();

    for (int k = 0; k <= T_LEN; k++) {
        if (k < T_LEN) {
            float a00 = bs[txc], a01 = bs[txc+1], a02 = bs[txc+2], a03 = bs[txc+3];
            float a10 = a00, a11 = a01, a12 = a02, a13 = a03;
            const float* hprev = g_h0T + (size_t)((k + 1) & 1) * 65536;
            float xr[8];
            size_t xbase = (size_t)k * BATCH * ADIM;
#pragma unroll
            for (int q = 0; q < 8; q++) {
                int e = tid + q * 256;
                xr[q] = __ldg(&x[xbase + (size_t)(row0 + (e >> 5)) * ADIM + (e & 31)]);
            }
            float4 p0, p1;
            for (int ch = 0; ch < 5; ch++) {
                float* buf = HsT + (ch & 1) * 2176;
                if (ch == 0) {
#pragma unroll
                    for (int q = 0; q < 8; q++) {
                        int e = tid + q * 256;
                        buf[(e & 31) * HPITCH + (e >> 5)] = xr[q];
                    }
                } else {
                    *(float4*)&buf[kk0 * HPITCH + b40] = p0;
                    *(float4*)&buf[kk1 * HPITCH + b41] = p1;
                }
                if (ch < 4) {
                    int kb = ch * 32;
                    p0 = __ldcg((const float4*)&hprev[(kb + kk0) * 512 + row0 + b40]);
                    p1 = __ldcg((const float4*)&hprev[(kb + kk1) * 512 + row0 + b41]);
                }
                __syncthreads();
                int wb = ch * 1024;
#pragma unroll
                for (int kk = 0; kk < 32; kk++) {
                    float2 av = *(const float2*)&buf[kk * HPITCH + tyb];
                    float4 bv = *(const float4*)&W0s[wb + kk * 32 + txc];
                    a00 += av.x * bv.x; a01 += av.x * bv.y; a02 += av.x * bv.z; a03 += av.x * bv.w;
                    a10 += av.y * bv.x; a11 += av.y * bv.y; a12 += av.y * bv.z; a13 += av.y * bv.w;
                }
            }
            __syncthreads();
            float* hcur = g_h0T + (size_t)(k & 1) * 65536;
            {
                float ig = 1.f / (1.f + expf(-a00));
                float fg = 1.f / (1.f + expf(-a01));
                float gg = tanhf(a02);
                float og = 1.f / (1.f + expf(-a03));
                float c = fg * c0a + ig * gg; c0a = c;
                hcur[j * 512 + row0 + tyb] = og * tanhf(c);
            }
            {
                float ig = 1.f / (1.f + expf(-a10));
                float fg = 1.f / (1.f + expf(-a11));
                float gg = tanhf(a12);
                float og = 1.f / (1.f + expf(-a13));
                float c = fg * c0b + ig * gg; c0b = c;
                hcur[j * 512 + row0 + tyb + 1] = og * tanhf(c);
            }
        }
        if (k >= 1) {
            int t1 = k - 1;
            float a00 = bs[32+txc], a01 = bs[33+txc], a02 = bs[34+txc], a03 = bs[35+txc];
            float a10 = a00, a11 = a01, a12 = a02, a13 = a03;
            const float* h0in = g_h0T + (size_t)(t1 & 1) * 65536;
            const float* h1in = g_h1T + (size_t)(k & 1) * 65536;
            float4 p0 = __ldcg((const float4*)&h0in[kk0 * 512 + row0 + b40]);
            float4 p1 = __ldcg((const float4*)&h0in[kk1 * 512 + row0 + b41]);
            for (int ch = 0; ch < 8; ch++) {
                float* buf = HsT + (ch & 1) * 2176;
                *(float4*)&buf[kk0 * HPITCH + b40] = p0;
                *(float4*)&buf[kk1 * HPITCH + b41] = p1;
                if (ch < 7) {
                    const float* src = (ch + 1 < 4) ? h0in : h1in;
                    int kb = ((ch + 1) & 3) * 32;
                    p0 = __ldcg((const float4*)&src[(kb + kk0) * 512 + row0 + b40]);
                    p1 = __ldcg((const float4*)&src[(kb + kk1) * 512 + row0 + b41]);
                }
                __syncthreads();
                int wb = ch * 1024;
#pragma unroll
                for (int kk = 0; kk < 32; kk++) {
                    float2 av = *(const float2*)&buf[kk * HPITCH + tyb];
                    float4 bv = *(const float4*)&W1s[wb + kk * 32 + txc];
                    a00 += av.x * bv.x; a01 += av.x * bv.y; a02 += av.x * bv.z; a03 += av.x * bv.w;
                    a10 += av.y * bv.x; a11 += av.y * bv.y; a12 += av.y * bv.z; a13 += av.y * bv.w;
                }
            }
            float* h1cur = g_h1T + (size_t)((k & 1) ^ 1) * 65536;
            {
                float ig = 1.f / (1.f + expf(-a00));
                float fg = 1.f / (1.f + expf(-a01));
                float gg = tanhf(a02);
                float og = 1.f / (1.f + expf(-a03));
                float c = fg * c1a + ig * gg; c1a = c;
                float h = og * tanhf(c);
                h1cur[j * 512 + row0 + tyb] = h;
                g_h1all[((size_t)t1 * 512 + row0 + tyb) * 128 + j] = h;
            }
            {
                float ig = 1.f / (1.f + expf(-a10));
                float fg = 1.f / (1.f + expf(-a11));
                float gg = tanhf(a12);
                float og = 1.f / (1.f + expf(-a13));
                float c = fg * c1b + ig * gg; c1b = c;
                float h = og * tanhf(c);
                h1cur[j * 512 + row0 + tyb + 1] = h;
                g_h1all[((size_t)t1 * 512 + row0 + tyb + 1) * 128 + j] = h;
            }
        }
        __syncthreads();
        if (tid == 0) {
            __threadfence();
            unsigned gen = (unsigned)(k + 1);
            unsigned a = atomicAdd(&g_arrive, 1u);
            if (a == NBLK - 1) {
                atomicExch(&g_arrive, 0u);
                __threadfence();
                g_release = gen;
            } else {
                while (g_release < gen) { }
            }
        }
        __syncthreads();
    }
}

// ---------------- logits + softmax ----------------
__global__ void logits_kernel(const float* __restrict__ Wlin, const float* __restrict__ blin)
{
    int row = blockIdx.x * 4 + (threadIdx.x >> 5);
    int lane = threadIdx.x & 31;
    const float* h = g_h1all + (size_t)row * HID;
    float v0 = h[lane], v1 = h[lane + 32], v2 = h[lane + 64], v3 = h[lane + 96];
    float lg[3];
#pragma unroll
    for (int kk = 0; kk < 3; kk++) {
        const float* w = Wlin + kk * HID;
        float d = v0 * w[lane] + v1 * w[lane + 32] + v2 * w[lane + 64] + v3 * w[lane + 96];
#pragma unroll
        for (int off = 16; off > 0; off >>= 1) d += __shfl_xor_sync(0xffffffffu, d, off);
        lg[kk] = d + blin[kk];
    }
    if (lane == 0) {
        float m = fmaxf(lg[0], fmaxf(lg[1], lg[2]));
        float e0 = expf(lg[0] - m), e1 = expf(lg[1] - m), e2 = expf(lg[2] - m);
        float s = 1.f / (e0 + e1 + e2);
        float* w = g_wall + ((size_t)row + BATCH) * 3;
        w[0] = e0 * s; w[1] = e1 * s; w[2] = e2 * s;
    }
}

// ---------------- edge rows: AS row 0, CS row T ----------------
__global__ void edge_kernel(const float* __restrict__ AK, const float* __restrict__ CK,
                            float* __restrict__ out)
{
    int NTOT = 512 * 256 + 512 * 512;
    int stride = gridDim.x * blockDim.x;
    for (int idx = blockIdx.x * blockDim.x + threadIdx.x; idx < NTOT; idx += stride) {
        if (idx < 131072) {
            int b = idx >> 8, e = idx & 255;
            out[OFF_AS + (size_t)b * 256 + e] = AK[e] + AK[256 + e] + AK[512 + e];
        } else {
            int i2 = idx - 131072;
            int b = i2 >> 9, e = i2 & 511;
            const float* w = g_wall + ((size_t)T_LEN * BATCH + b) * 3;
            out[OFF_CS + ((size_t)T_LEN * BATCH + b) * 512 + e] =
                w[0] * CK[e] + w[1] * CK[512 + e] + w[2] * CK[1024 + e];
        }
    }
}

// ---------------- Kalman: warp-per-batch, Woodbury 16x16 solve ----------------
__global__ void __launch_bounds__(128) kalman_kernel(
    const float* __restrict__ as_, const float* __restrict__ AK,
    const float* __restrict__ CK, const float* __restrict__ im,
    const float* __restrict__ ic, float* __restrict__ out)
{
    extern __shared__ float sm[];
    float* sCK  = sm;             // 1632
    float* sAK  = sCK + 1632;     // 816
    float* sCKR = sAK + 816;      // 1584 (3 x 16x33)
    float* sM   = sCKR + 1584;    // 2448 (9 x 16x17)
    float* sQ   = sM + 2448;      // 272
    float* wsAll = sQ + 272;      // per warp 1952

    int tid = threadIdx.x, wid = tid >> 5, l = tid & 31;
    int b = blockIdx.x * 4 + wid;
    float* P    = wsAll + wid * 1952;
    float* Pf   = P + 272;
    float* A    = Pf + 272;
    float* Tm   = A + 272;
    float* X    = Tm + 272;
    float* DC   = X + 272;
    float* Fm   = DC + 272;
    float* sres = Fm + 272;   // 32
    float* su   = sres + 32;  // 16 (+pad to 1952)

    for (int e = tid; e < 1536; e += 128) {
        int kk = e >> 9, rem = e & 511;
        sCK[kk * 544 + (rem >> 4) * 17 + (rem & 15)] = CK[e];
    }
    for (int e = tid; e < 768; e += 128) {
        int kk = e >> 8, rem = e & 255;
        sAK[kk * 272 + (rem >> 4) * 17 + (rem & 15)] = AK[e];
    }
    for (int e = tid; e < 1536; e += 128) {
        int kk = e >> 9, rem = e & 511;
        sCKR[kk * 528 + (rem >> 5) * 33 + (rem & 31)] = g_CKR[e];
    }
    for (int e = tid; e < 2304; e += 128) {
        int jk = e >> 8, rem = e & 255;
        sM[jk * 272 + (rem >> 4) * 17 + (rem & 15)] = g_M[e];
    }
    for (int e = tid; e < 256; e += 128) sQ[(e >> 4) * 17 + (e & 15)] = g_Q[e];
    for (int e = l; e < 256; e += 32) P[(e >> 4) * 17 + (e & 15)] = ic[e];
    float m[16];
#pragma unroll
    for (int k = 0; k < 16; k++) m[k] = im[k];
    __syncthreads();

    int i_ = l >> 1, j0 = (l & 1) * 8;

    for (int t = 0; t < T_LEN; t++) {
        size_t row = (size_t)t * BATCH + b;
        const float* wl = g_wall + row * 3;
        float w0 = wl[0], w1 = wl[1], w2 = wl[2];
        const float* wa = g_wall + ((size_t)(t + 1) * BATCH + b) * 3;
        float a0 = __ldg(&wa[0]), a1 = __ldg(&wa[1]), a2 = __ldg(&wa[2]);
        float aobs = __ldg(&as_[row * 32 + l]);

        // C row l + CS out
        float c[16];
#pragma unroll
        for (int k = 0; k < 16; k++)
            c[k] = w0 * sCK[l*17+k] + w1 * sCK[544 + l*17+k] + w2 * sCK[1088 + l*17+k];
        {
            float4* dst = (float4*)(out + OFF_CS + row * 512 + l * 16);
            dst[0] = make_float4(c[0], c[1], c[2], c[3]);
            dst[1] = make_float4(c[4], c[5], c[6], c[7]);
            dst[2] = make_float4(c[8], c[9], c[10], c[11]);
            dst[3] = make_float4(c[12], c[13], c[14], c[15]);
        }
        // res
        float res = aobs;
#pragma unroll
        for (int k = 0; k < 16; k++) res -= c[k] * m[k];
        sres[l] = res;

        // DC = sum_{j,k} w_j w_k M_jk  (8 elems/lane)
        float cf0 = w0*w0, cf1 = w0*w1, cf2 = w0*w2;
        float cf3 = w1*w0, cf4 = w1*w1, cf5 = w1*w2;
        float cf6 = w2*w0, cf7 = w2*w1, cf8 = w2*w2;
#pragma unroll
        for (int jj = 0; jj < 8; jj++) {
            int idx = i_ * 17 + j0 + jj;
            float s = cf0 * sM[idx]        + cf1 * sM[272 + idx]  + cf2 * sM[544 + idx]
                    + cf3 * sM[816 + idx]  + cf4 * sM[1088 + idx] + cf5 * sM[1360 + idx]
                    + cf6 * sM[1632 + idx] + cf7 * sM[1904 + idx] + cf8 * sM[2176 + idx];
            DC[idx] = s;
        }
        __syncwarp();
        // F = I + P @ DC (8/lane) ; A = sum w_a AK (8/lane) + AS out
        {
            float v[8], u8[8];
#pragma unroll
            for (int jj = 0; jj < 8; jj++) {
                int jc = j0 + jj;
                float s = (i_ == jc) ? 1.f : 0.f;
#pragma unroll
                for (int k = 0; k < 16; k++) s += P[i_*17+k] * DC[k*17+jc];
                v[jj] = s;
                u8[jj] = a0 * sAK[i_*17+jc] + a1 * sAK[272 + i_*17+jc] + a2 * sAK[544 + i_*17+jc];
                A[i_*17+jc] = u8[jj];
            }
#pragma unroll
            for (int jj = 0; jj < 8; jj++) Fm[i_*17+j0+jj] = v[jj];
            float4* d2 = (float4*)(out + OFF_AS + ((size_t)(t + 1) * BATCH + b) * 256 + l * 8);
            d2[0] = make_float4(u8[0], u8[1], u8[2], u8[3]);
            d2[1] = make_float4(u8[4], u8[5], u8[6], u8[7]);
        }
        __syncwarp();
        // GJ on [F | P]: lane<16 -> F col l ; lane>=16 -> P col (l-16). 16 pivots.
        float col[16];
        if (l < 16) {
#pragma unroll
            for (int r = 0; r < 16; r++) col[r] = Fm[r*17 + l];
        } else {
#pragma unroll
            for (int r = 0; r < 16; r++) col[r] = P[r*17 + (l - 16)];
        }
#pragma unroll
        for (int kg = 0; kg < 16; kg++) {
            float pv = __shfl_sync(0xffffffffu, col[kg], kg);
            float pinv = __fdividef(1.0f, pv);
            float pr = col[kg] * pinv;
            col[kg] = pr;
#pragma unroll
            for (int r = 0; r < 16; r++) {
                if (r == kg) continue;
                float cc = __shfl_sync(0xffffffffu, col[r], kg);
                col[r] -= cc * pr;
            }
        }
        if (l >= 16) {
#pragma unroll
            for (int r = 0; r < 16; r++) Tm[r*17 + (l - 16)] = col[r];  // P_f unsym
        }
        // u = D res (lanes<16)
        if (l < 16) {
            float t0 = 0.f, t1 = 0.f, t2 = 0.f;
#pragma unroll
            for (int a = 0; a < 32; a++) {
                float ra = sres[a];
                t0 += sCKR[l*33+a] * ra;
                t1 += sCKR[528 + l*33+a] * ra;
                t2 += sCKR[1056 + l*33+a] * ra;
            }
            su[l] = w0 * t0 + w1 * t1 + w2 * t2;
        }
        __syncwarp();
        // sym Pf + covs out
        {
            float v[8];
#pragma unroll
            for (int jj = 0; jj < 8; jj++) {
                int jc = j0 + jj;
                v[jj] = 0.5f * (Tm[i_*17+jc] + Tm[jc*17+i_]);
                Pf[i_*17+jc] = v[jj];
            }
            float4* d1 = (float4*)(out + OFF_COVS + row * 256 + l * 8);
            d1[0] = make_float4(v[0], v[1], v[2], v[3]);
            d1[1] = make_float4(v[4], v[5], v[6], v[7]);
        }
        __syncwarp();
        // m_f = m + Pf @ u
        float mf = 0.f;
        if (l < 16) {
            mf = m[l];
#pragma unroll
            for (int z = 0; z < 16; z++) mf += Pf[l*17+z] * su[z];
            out[OFF_MEANS + row * 16 + l] = mf;
        }
#pragma unroll
        for (int k = 0; k < 16; k++) m[k] = __shfl_sync(0xffffffffu, mf, k);
        // Tm = A @ Pf ; m_p
        {
            float v[8];
#pragma unroll
            for (int jj = 0; jj < 8; jj++) {
                int jc = j0 + jj;
                float s = 0.f;
#pragma unroll
                for (int k = 0; k < 16; k++) s += A[i_*17+k] * Pf[k*17+jc];
                v[jj] = s;
            }
#pragma unroll
            for (int jj = 0; jj < 8; jj++) Tm[i_*17+j0+jj] = v[jj];
        }
        float mp = 0.f;
        if (l < 16) {
#pragma unroll
            for (int k = 0; k < 16; k++) mp += A[l*17+k] * m[k];
            out[OFF_NM + row * 16 + l] = mp;
        }
        __syncwarp();
        // Pp unsym = Tm @ A^T + Q -> X
        {
            float v[8];
#pragma unroll
            for (int jj = 0; jj < 8; jj++) {
                int jc = j0 + jj;
                float s = sQ[i_*17+jc];
#pragma unroll
                for (int k = 0; k < 16; k++) s += Tm[i_*17+k] * A[jc*17+k];
                v[jj] = s;
            }
#pragma unroll
            for (int jj = 0; jj < 8; jj++) X[i_*17+j0+jj] = v[jj];
        }
#pragma unroll
        for (int k = 0; k < 16; k++) m[k] = __shfl_sync(0xffffffffu, mp, k);
        __syncwarp();
        // sym Pp -> P, NC out
        {
            float v[8];
#pragma unroll
            for (int jj = 0; jj < 8; jj++) {
                int jc = j0 + jj;
                v[jj] = 0.5f * (X[i_*17+jc] + X[jc*17+i_]);
                P[i_*17+jc] = v[jj];
            }
            float4* d = (float4*)(out + OFF_NC + row * 256 + l * 8);
            d[0] = make_float4(v[0], v[1], v[2], v[3]);
            d[1] = make_float4(v[4], v[5], v[6], v[7]);
        }
        __syncwarp();
    }
}

extern "C" void kernel_launch(void* const* d_in, const int* in_sizes, int n_in,
                              void* d_out, int out_size) {
    const float* as_  = (const float*)d_in[0];
    const float* AK   = (const float*)d_in[1];
    const float* CK   = (const float*)d_in[2];
    const float* QL   = (const float*)d_in[3];
    const float* RL   = (const float*)d_in[4];
    const float* Wih0 = (const float*)d_in[5];
    const float* Whh0 = (const float*)d_in[6];
    const float* bih0 = (const float*)d_in[7];
    const float* bhh0 = (const float*)d_in[8];
    const float* Wih1 = (const float*)d_in[9];
    const float* Whh1 = (const float*)d_in[10];
    const float* bih1 = (const float*)d_in[11];
    const float* bhh1 = (const float*)d_in[12];
    const float* Wlin = (const float*)d_in[13];
    const float* blin = (const float*)d_in[14];
    const float* im   = (const float*)d_in[15];
    const float* ic   = (const float*)d_in[16];
    float* out = (float*)d_out;

    int smemL = (5120 + 8192 + 4352 + 64) * 4;
    int smemK = (1632 + 816 + 1584 + 2448 + 272 + 4 * 1952) * 4;
    cudaFuncSetAttribute(lstm_persistent, cudaFuncAttributeMaxDynamicSharedMemorySize, smemL);
    cudaFuncSetAttribute(kalman_kernel, cudaFuncAttributeMaxDynamicSharedMemorySize, smemK);

    prep_kernel<<<256, 256>>>(QL, RL, Wih0, Whh0, bih0, bhh0, Wih1, Whh1, bih1, bhh1);
    prep2_kernel<<<1, 256>>>(CK);
    lstm_persistent<<<NBLK, 256, smemL>>>(as_);
    logits_kernel<<<TB / 4, 128>>>(Wlin, blin);
    edge_kernel<<<1536, 256>>>(AK, CK, out);
    kalman_kernel<<<BATCH / 4, 128, smemK>>>(as_, AK, CK, im, ic, out);
}